// round 4
// baseline (speedup 1.0000x reference)
#include <cuda_runtime.h>
#include <cuda_bf16.h>
#include <math.h>
#include <stdint.h>

typedef unsigned short ushort_t;

// ---------------------------------------------------------------------------
// Scratch (device globals; no runtime allocation allowed)
// ---------------------------------------------------------------------------
__device__ float    g_KV[(size_t)32768 * 2048];     // [B*S, 2048]: K | V (fp32)
__device__ ushort_t g_srcH[(size_t)32768 * 1024];   // src bf16 hi
__device__ ushort_t g_srcL[(size_t)32768 * 1024];   // src bf16 lo
__device__ ushort_t g_wkvH[(size_t)2048 * 1024];    // [Wk|Wv]^T bf16 hi : [n][k]
__device__ ushort_t g_wkvL[(size_t)2048 * 1024];
__device__ float    g_Q [(size_t)1024 * 1024];
__device__ float    g_A [(size_t)1024 * 1024];
__device__ float    g_F1[(size_t)1024 * 1024];
__device__ float    g_T1[(size_t)1024 * 256];
__device__ float    g_X1[(size_t)1024 * 256];

// ---------------------------------------------------------------------------
// helpers
// ---------------------------------------------------------------------------
__device__ __forceinline__ void split2(float x0, float x1, uint32_t& hi, uint32_t& lo) {
    __nv_bfloat16 h0 = __float2bfloat16(x0), h1 = __float2bfloat16(x1);
    float r0 = x0 - __bfloat162float(h0);
    float r1 = x1 - __bfloat162float(h1);
    __nv_bfloat16 l0 = __float2bfloat16(r0), l1 = __float2bfloat16(r1);
    hi = (uint32_t)__bfloat16_as_ushort(h0) | ((uint32_t)__bfloat16_as_ushort(h1) << 16);
    lo = (uint32_t)__bfloat16_as_ushort(l0) | ((uint32_t)__bfloat16_as_ushort(l1) << 16);
}

__device__ __forceinline__ void mma16816(float* c, const uint32_t* a, uint32_t b0, uint32_t b1) {
    asm volatile(
        "mma.sync.aligned.m16n8k16.row.col.f32.bf16.bf16.f32 "
        "{%0,%1,%2,%3}, {%4,%5,%6,%7}, {%8,%9}, {%0,%1,%2,%3};"
        : "+f"(c[0]), "+f"(c[1]), "+f"(c[2]), "+f"(c[3])
        : "r"(a[0]), "r"(a[1]), "r"(a[2]), "r"(a[3]), "r"(b0), "r"(b1));
}

__device__ __forceinline__ void cp16(void* sdst, const void* gsrc) {
    uint32_t s = (uint32_t)__cvta_generic_to_shared(sdst);
    asm volatile("cp.async.cg.shared.global [%0], [%1], 16;" :: "r"(s), "l"(gsrc));
}

// ---------------------------------------------------------------------------
// pre-pass: fp32 -> bf16 hi/lo (flat, float4 granularity)
// ---------------------------------------------------------------------------
__global__ __launch_bounds__(256) void convert_src_kernel(
    const float* __restrict__ x, ushort_t* __restrict__ H, ushort_t* __restrict__ L, int n4)
{
    int i = blockIdx.x * blockDim.x + threadIdx.x;
    if (i >= n4) return;
    float4 v = ((const float4*)x)[i];
    uint32_t h0, l0, h1, l1;
    split2(v.x, v.y, h0, l0);
    split2(v.z, v.w, h1, l1);
    ((uint2*)H)[i] = make_uint2(h0, h1);
    ((uint2*)L)[i] = make_uint2(l0, l1);
}

// ---------------------------------------------------------------------------
// pre-pass: WT[n][k] = (n<1024 ? Wk[k][n] : Wv[k][n-1024]) -> bf16 hi/lo
// grid (2048/32, 1024/32), block (32,8)
// ---------------------------------------------------------------------------
__global__ __launch_bounds__(256) void conv_wkv_kernel(
    const float* __restrict__ Wk, const float* __restrict__ Wv,
    ushort_t* __restrict__ H, ushort_t* __restrict__ L)
{
    __shared__ float tile[32][33];
    const int n0 = blockIdx.x * 32, k0 = blockIdx.y * 32;
    const float* W = (n0 < 1024) ? Wk : Wv;
    const int nofs = (n0 < 1024) ? n0 : n0 - 1024;
    for (int r = threadIdx.y; r < 32; r += 8)
        tile[r][threadIdx.x] = W[(size_t)(k0 + r) * 1024 + nofs + threadIdx.x];
    __syncthreads();
    for (int r = threadIdx.y; r < 32; r += 8) {
        float v = tile[threadIdx.x][r];
        __nv_bfloat16 h = __float2bfloat16(v);
        float rr = v - __bfloat162float(h);
        __nv_bfloat16 l = __float2bfloat16(rr);
        size_t o = (size_t)(n0 + r) * 1024 + k0 + threadIdx.x;
        H[o] = __bfloat16_as_ushort(h);
        L[o] = __bfloat16_as_ushort(l);
    }
}

// ---------------------------------------------------------------------------
// Fused KV GEMM: C[32768,2048] = srcBF16 @ WkvT^T + bias(bk|bv)
// A: bf16 hi/lo [M][1024], B: bf16 hi/lo [N][K] (transposed).
// Block tile 128x128, BK=32, cp.async double-buffered, 256 threads.
// Dynamic smem: 8 * 128*40 halves = 81920 B.
// ---------------------------------------------------------------------------
#define TP 40              // smem pitch in halves (32 + 8 pad)
#define TILE_H (128 * TP)  // halves per component buffer

__device__ __forceinline__ void kv_load_tiles(
    ushort_t* AsH, ushort_t* AsL, ushort_t* BsH, ushort_t* BsL,
    const ushort_t* __restrict__ srcH, const ushort_t* __restrict__ srcL,
    const ushort_t* __restrict__ wtH,  const ushort_t* __restrict__ wtL,
    int r0, int c0, int kb, int tid)
{
#pragma unroll
    for (int j = 0; j < 2; j++) {
        int cc  = tid + 256 * j;         // 0..511
        int row = cc >> 2;
        int c16 = (cc & 3) * 8;          // halves
        size_t ga = (size_t)(r0 + row) * 1024 + kb + c16;
        cp16(&AsH[row * TP + c16], srcH + ga);
        cp16(&AsL[row * TP + c16], srcL + ga);
        size_t gb = (size_t)(c0 + row) * 1024 + kb + c16;
        cp16(&BsH[row * TP + c16], wtH + gb);
        cp16(&BsL[row * TP + c16], wtL + gb);
    }
}

__global__ __launch_bounds__(256) void gemm_kv_bf16(
    const ushort_t* __restrict__ srcH, const ushort_t* __restrict__ srcL,
    const ushort_t* __restrict__ wtH,  const ushort_t* __restrict__ wtL,
    const float* __restrict__ bk, const float* __restrict__ bv,
    float* __restrict__ C)
{
    extern __shared__ ushort_t smem[];
    ushort_t* AsH = smem;
    ushort_t* AsL = AsH + 2 * TILE_H;
    ushort_t* BsH = AsL + 2 * TILE_H;
    ushort_t* BsL = BsH + 2 * TILE_H;

    const int tid  = threadIdx.x;
    const int lane = tid & 31;
    const int wid  = tid >> 5;
    const int wm   = wid & 3;
    const int wn   = wid >> 2;
    const int g    = lane >> 2;
    const int tig  = lane & 3;

    const int r0 = blockIdx.y * 128;
    const int c0 = blockIdx.x * 128;

    float acc[2][8][4];
#pragma unroll
    for (int mt = 0; mt < 2; mt++)
#pragma unroll
        for (int nt = 0; nt < 8; nt++)
#pragma unroll
            for (int j = 0; j < 4; j++) acc[mt][nt][j] = 0.f;

    kv_load_tiles(AsH, AsL, BsH, BsL, srcH, srcL, wtH, wtL, r0, c0, 0, tid);
    asm volatile("cp.async.commit_group;" ::: "memory");

    int buf = 0;
    for (int it = 0; it < 32; it++) {
        if (it < 31) {
            int nb = buf ^ 1;
            kv_load_tiles(AsH + nb * TILE_H, AsL + nb * TILE_H,
                          BsH + nb * TILE_H, BsL + nb * TILE_H,
                          srcH, srcL, wtH, wtL, r0, c0, (it + 1) * 32, tid);
            asm volatile("cp.async.commit_group;" ::: "memory");
            asm volatile("cp.async.wait_group 1;" ::: "memory");
        } else {
            asm volatile("cp.async.wait_group 0;" ::: "memory");
        }
        __syncthreads();

        const ushort_t* aH = AsH + buf * TILE_H;
        const ushort_t* aL = AsL + buf * TILE_H;
        const ushort_t* bH = BsH + buf * TILE_H;
        const ushort_t* bL = BsL + buf * TILE_H;

#pragma unroll
        for (int ks = 0; ks < 32; ks += 16) {
            uint32_t AHf[2][4], ALf[2][4];
#pragma unroll
            for (int mt = 0; mt < 2; mt++) {
                int rA = wm * 32 + mt * 16 + g;
                int cA = ks + tig * 2;
                AHf[mt][0] = *(const uint32_t*)&aH[rA * TP + cA];
                AHf[mt][1] = *(const uint32_t*)&aH[(rA + 8) * TP + cA];
                AHf[mt][2] = *(const uint32_t*)&aH[rA * TP + cA + 8];
                AHf[mt][3] = *(const uint32_t*)&aH[(rA + 8) * TP + cA + 8];
                ALf[mt][0] = *(const uint32_t*)&aL[rA * TP + cA];
                ALf[mt][1] = *(const uint32_t*)&aL[(rA + 8) * TP + cA];
                ALf[mt][2] = *(const uint32_t*)&aL[rA * TP + cA + 8];
                ALf[mt][3] = *(const uint32_t*)&aL[(rA + 8) * TP + cA + 8];
            }
#pragma unroll
            for (int nt = 0; nt < 8; nt++) {
                int n  = wn * 64 + nt * 8 + g;
                int kk = ks + tig * 2;
                uint32_t bH0 = *(const uint32_t*)&bH[n * TP + kk];
                uint32_t bH1 = *(const uint32_t*)&bH[n * TP + kk + 8];
                uint32_t bL0 = *(const uint32_t*)&bL[n * TP + kk];
                uint32_t bL1 = *(const uint32_t*)&bL[n * TP + kk + 8];
#pragma unroll
                for (int mt = 0; mt < 2; mt++) {
                    mma16816(acc[mt][nt], AHf[mt], bH0, bH1);
                    mma16816(acc[mt][nt], AHf[mt], bL0, bL1);
                    mma16816(acc[mt][nt], ALf[mt], bH0, bH1);
                }
            }
        }
        __syncthreads();
        buf ^= 1;
    }

    // epilogue
#pragma unroll
    for (int mt = 0; mt < 2; mt++) {
        int r = r0 + wm * 32 + mt * 16 + g;
#pragma unroll
        for (int nt = 0; nt < 8; nt++) {
            int col = c0 + wn * 64 + nt * 8 + tig * 2;
            float b0 = (col < 1024) ? bk[col] : bv[col - 1024];
            float b1 = (col + 1 < 1024) ? bk[col + 1] : bv[col + 1 - 1024];
            *(float2*)(C + (size_t)r * 2048 + col) =
                make_float2(acc[mt][nt][0] + b0, acc[mt][nt][1] + b1);
            *(float2*)(C + (size_t)(r + 8) * 2048 + col) =
                make_float2(acc[mt][nt][2] + b0, acc[mt][nt][3] + b1);
        }
    }
}

// ---------------------------------------------------------------------------
// Small GEMM (fp32 in, in-loop bf16 hi/lo split) — proven R3 kernel.
// ---------------------------------------------------------------------------
#define A_PITCH 40
#define B_PITCH 136

template<bool RELU>
__global__ __launch_bounds__(256) void gemm_tc(
    const float* __restrict__ A, int lda,
    const float* __restrict__ W, int ldb,
    const float* __restrict__ bias,
    float* __restrict__ C, int ldc, int K)
{
    __shared__ unsigned short AsH[128 * A_PITCH];
    __shared__ unsigned short AsL[128 * A_PITCH];
    __shared__ unsigned short BsH[32 * B_PITCH];
    __shared__ unsigned short BsL[32 * B_PITCH];

    const int tid  = threadIdx.x;
    const int lane = tid & 31;
    const int wid  = tid >> 5;
    const int wm   = wid & 3;
    const int wn   = wid >> 2;
    const int g    = lane >> 2;
    const int tig  = lane & 3;

    const int r0 = blockIdx.y * 128;
    const int c0 = blockIdx.x * 128;

    float acc[2][8][4];
#pragma unroll
    for (int mt = 0; mt < 2; mt++)
#pragma unroll
        for (int nt = 0; nt < 8; nt++)
#pragma unroll
            for (int j = 0; j < 4; j++) acc[mt][nt][j] = 0.f;

    for (int kb = 0; kb < K; kb += 32) {
#pragma unroll
        for (int i = 0; i < 4; i++) {
            int flat = tid + 256 * i;
            int row = flat >> 3;
            int kc  = (flat & 7) * 4;
            float4 a4 = *(const float4*)(A + (size_t)(r0 + row) * lda + kb + kc);
            uint32_t hi, lo;
            split2(a4.x, a4.y, hi, lo);
            *(uint32_t*)&AsH[row * A_PITCH + kc] = hi;
            *(uint32_t*)&AsL[row * A_PITCH + kc] = lo;
            split2(a4.z, a4.w, hi, lo);
            *(uint32_t*)&AsH[row * A_PITCH + kc + 2] = hi;
            *(uint32_t*)&AsL[row * A_PITCH + kc + 2] = lo;
        }
#pragma unroll
        for (int i = 0; i < 4; i++) {
            int flat = tid + 256 * i;
            int kr = flat >> 5;
            int nc = (flat & 31) * 4;
            float4 b4 = *(const float4*)(W + (size_t)(kb + kr) * ldb + c0 + nc);
            uint32_t hi, lo;
            split2(b4.x, b4.y, hi, lo);
            *(uint32_t*)&BsH[kr * B_PITCH + nc] = hi;
            *(uint32_t*)&BsL[kr * B_PITCH + nc] = lo;
            split2(b4.z, b4.w, hi, lo);
            *(uint32_t*)&BsH[kr * B_PITCH + nc + 2] = hi;
            *(uint32_t*)&BsL[kr * B_PITCH + nc + 2] = lo;
        }
        __syncthreads();

#pragma unroll
        for (int ks = 0; ks < 32; ks += 16) {
            uint32_t aH[2][4], aL[2][4];
#pragma unroll
            for (int mt = 0; mt < 2; mt++) {
                int rA = wm * 32 + mt * 16 + g;
                int cA = ks + tig * 2;
                aH[mt][0] = *(const uint32_t*)&AsH[rA * A_PITCH + cA];
                aH[mt][1] = *(const uint32_t*)&AsH[(rA + 8) * A_PITCH + cA];
                aH[mt][2] = *(const uint32_t*)&AsH[rA * A_PITCH + cA + 8];
                aH[mt][3] = *(const uint32_t*)&AsH[(rA + 8) * A_PITCH + cA + 8];
                aL[mt][0] = *(const uint32_t*)&AsL[rA * A_PITCH + cA];
                aL[mt][1] = *(const uint32_t*)&AsL[(rA + 8) * A_PITCH + cA];
                aL[mt][2] = *(const uint32_t*)&AsL[rA * A_PITCH + cA + 8];
                aL[mt][3] = *(const uint32_t*)&AsL[(rA + 8) * A_PITCH + cA + 8];
            }
#pragma unroll
            for (int nt = 0; nt < 8; nt++) {
                int col = wn * 64 + nt * 8 + g;
                int rb  = (ks + tig * 2) * B_PITCH + col;
                uint32_t bH0 = (uint32_t)BsH[rb] | ((uint32_t)BsH[rb + B_PITCH] << 16);
                uint32_t bL0 = (uint32_t)BsL[rb] | ((uint32_t)BsL[rb + B_PITCH] << 16);
                int rb8 = rb + 8 * B_PITCH;
                uint32_t bH1 = (uint32_t)BsH[rb8] | ((uint32_t)BsH[rb8 + B_PITCH] << 16);
                uint32_t bL1 = (uint32_t)BsL[rb8] | ((uint32_t)BsL[rb8 + B_PITCH] << 16);
#pragma unroll
                for (int mt = 0; mt < 2; mt++) {
                    mma16816(acc[mt][nt], aH[mt], bH0, bH1);
                    mma16816(acc[mt][nt], aH[mt], bL0, bL1);
                    mma16816(acc[mt][nt], aL[mt], bH0, bH1);
                }
            }
        }
        __syncthreads();
    }

#pragma unroll
    for (int mt = 0; mt < 2; mt++) {
        int r = r0 + wm * 32 + mt * 16 + g;
#pragma unroll
        for (int nt = 0; nt < 8; nt++) {
            int col = c0 + wn * 64 + nt * 8 + tig * 2;
            float b0 = bias[col], b1 = bias[col + 1];
            float v0 = acc[mt][nt][0] + b0;
            float v1 = acc[mt][nt][1] + b1;
            float v2 = acc[mt][nt][2] + b0;
            float v3 = acc[mt][nt][3] + b1;
            if (RELU) {
                v0 = fmaxf(v0, 0.f); v1 = fmaxf(v1, 0.f);
                v2 = fmaxf(v2, 0.f); v3 = fmaxf(v3, 0.f);
            }
            *(float2*)(C + (size_t)r * ldc + col)       = make_float2(v0, v1);
            *(float2*)(C + (size_t)(r + 8) * ldc + col) = make_float2(v2, v3);
        }
    }
}

// ---------------------------------------------------------------------------
// Flash attention, split-T: one block per (b,h,half), 32 queries each.
// grid = 512, 256 threads.
// ---------------------------------------------------------------------------
__global__ __launch_bounds__(256) void attn_kernel(
    const float* __restrict__ Q,
    const float* __restrict__ KV,
    float* __restrict__ Aout)
{
    __shared__ float Qs[32][64];
    __shared__ float Ks[32][65];
    __shared__ float Vs[32][64];
    __shared__ float Ss[32][33];

    const int bh = blockIdx.x >> 1;
    const int half = blockIdx.x & 1;
    const int b = bh >> 4, h = bh & 15;
    const float* Qb = Q  + (size_t)(b * 64 + half * 32) * 1024 + h * 64;
    const float* Kb = KV + (size_t)b * 2048 * 2048 + h * 64;
    const float* Vb = Kb + 1024;

    const int tid = threadIdx.x;
    const int tx = tid & 15, ty = tid >> 4;

    for (int f = tid; f < 2048; f += 256) {
        int t = f >> 6, d = f & 63;
        Qs[t][d] = Qb[(size_t)t * 1024 + d] * 0.125f;
    }

    float out[2][4];
    float m[2], l[2];
#pragma unroll
    for (int i = 0; i < 2; i++) {
        m[i] = -1e30f; l[i] = 0.f;
#pragma unroll
        for (int j = 0; j < 4; j++) out[i][j] = 0.f;
    }
    __syncthreads();

    for (int s0 = 0; s0 < 2048; s0 += 32) {
        for (int f = tid; f < 2048; f += 256) {
            int s = f >> 6, d = f & 63;
            size_t gidx = (size_t)(s0 + s) * 2048 + d;
            Ks[s][d] = Kb[gidx];
            Vs[s][d] = Vb[gidx];
        }
        __syncthreads();

        float r[2][2];
#pragma unroll
        for (int i = 0; i < 2; i++) { r[i][0] = 0.f; r[i][1] = 0.f; }
#pragma unroll 8
        for (int d = 0; d < 64; d++) {
            float k0 = Ks[tx][d];
            float k1 = Ks[tx + 16][d];
#pragma unroll
            for (int i = 0; i < 2; i++) {
                float q = Qs[ty + 16 * i][d];
                r[i][0] = fmaf(q, k0, r[i][0]);
                r[i][1] = fmaf(q, k1, r[i][1]);
            }
        }

#pragma unroll
        for (int i = 0; i < 2; i++) {
            int t = ty + 16 * i;
            float cm = fmaxf(r[i][0], r[i][1]);
#pragma unroll
            for (int off = 8; off > 0; off >>= 1)
                cm = fmaxf(cm, __shfl_xor_sync(0xffffffffu, cm, off, 16));
            float mn = fmaxf(m[i], cm);
            float f_old = __expf(m[i] - mn);
            float p0 = __expf(r[i][0] - mn);
            float p1 = __expf(r[i][1] - mn);
            Ss[t][tx]      = p0;
            Ss[t][tx + 16] = p1;
            float cs = p0 + p1;
#pragma unroll
            for (int off = 8; off > 0; off >>= 1)
                cs += __shfl_xor_sync(0xffffffffu, cs, off, 16);
            l[i] = l[i] * f_old + cs;
            m[i] = mn;
#pragma unroll
            for (int j = 0; j < 4; j++) out[i][j] *= f_old;
        }
        __syncthreads();

#pragma unroll 4
        for (int s = 0; s < 32; s++) {
            float4 v = *(const float4*)&Vs[s][tx * 4];
#pragma unroll
            for (int i = 0; i < 2; i++) {
                float p = Ss[ty + 16 * i][s];
                out[i][0] = fmaf(p, v.x, out[i][0]);
                out[i][1] = fmaf(p, v.y, out[i][1]);
                out[i][2] = fmaf(p, v.z, out[i][2]);
                out[i][3] = fmaf(p, v.w, out[i][3]);
            }
        }
        __syncthreads();
    }

#pragma unroll
    for (int i = 0; i < 2; i++) {
        int t = ty + 16 * i;
        float inv = 1.f / l[i];
        float* Ap = Aout + (size_t)(b * 64 + half * 32 + t) * 1024 + h * 64 + tx * 4;
#pragma unroll
        for (int j = 0; j < 4; j++) Ap[j] = out[i][j] * inv;
    }
}

// ---------------------------------------------------------------------------
// out[row] = LayerNorm(pre[row] + res[row]) * g + b   (row length 256)
// ---------------------------------------------------------------------------
__global__ __launch_bounds__(256) void add_ln_kernel(
    const float* __restrict__ pre,
    const float* __restrict__ res,
    const float* __restrict__ g,
    const float* __restrict__ bta,
    float* __restrict__ out)
{
    const int row = blockIdx.x;
    const int t = threadIdx.x;
    const size_t idx = (size_t)row * 256 + t;

    float v = pre[idx] + res[idx];
    float s = v, s2 = v * v;
#pragma unroll
    for (int off = 16; off > 0; off >>= 1) {
        s  += __shfl_xor_sync(0xffffffffu, s,  off);
        s2 += __shfl_xor_sync(0xffffffffu, s2, off);
    }
    __shared__ float rs[8], rs2[8];
    const int w = t >> 5, lane = t & 31;
    if (lane == 0) { rs[w] = s; rs2[w] = s2; }
    __syncthreads();
    if (t < 32) {
        s  = (t < 8) ? rs[t]  : 0.f;
        s2 = (t < 8) ? rs2[t] : 0.f;
#pragma unroll
        for (int off = 4; off > 0; off >>= 1) {
            s  += __shfl_xor_sync(0xffffffffu, s,  off);
            s2 += __shfl_xor_sync(0xffffffffu, s2, off);
        }
        if (t == 0) { rs[0] = s; rs2[0] = s2; }
    }
    __syncthreads();
    float mean = rs[0] * (1.f / 256.f);
    float var  = rs2[0] * (1.f / 256.f) - mean * mean;
    out[idx] = (v - mean) * rsqrtf(var + 1e-5f) * g[t] + bta[t];
}

// ---------------------------------------------------------------------------
extern "C" void kernel_launch(void* const* d_in, const int* in_sizes, int n_in,
                              void* d_out, int out_size)
{
    const float* src  = (const float*)d_in[0];
    const float* tgt  = (const float*)d_in[1];
    const float* Wq   = (const float*)d_in[2];
    const float* bq   = (const float*)d_in[3];
    const float* Wk   = (const float*)d_in[4];
    const float* bk   = (const float*)d_in[5];
    const float* Wv   = (const float*)d_in[6];
    const float* bv   = (const float*)d_in[7];
    const float* Wo   = (const float*)d_in[8];
    const float* bo   = (const float*)d_in[9];
    const float* ln1g = (const float*)d_in[10];
    const float* ln1b = (const float*)d_in[11];
    const float* W1   = (const float*)d_in[12];
    const float* bf1  = (const float*)d_in[13];
    const float* W2   = (const float*)d_in[14];
    const float* bf2  = (const float*)d_in[15];
    const float* ln3g = (const float*)d_in[16];
    const float* ln3b = (const float*)d_in[17];
    float* out = (float*)d_out;

    float *KV, *Qp, *Ap, *F1, *T1, *X1;
    ushort_t *srcH, *srcL, *wkvH, *wkvL;
    cudaGetSymbolAddress((void**)&KV, g_KV);
    cudaGetSymbolAddress((void**)&Qp, g_Q);
    cudaGetSymbolAddress((void**)&Ap, g_A);
    cudaGetSymbolAddress((void**)&F1, g_F1);
    cudaGetSymbolAddress((void**)&T1, g_T1);
    cudaGetSymbolAddress((void**)&X1, g_X1);
    cudaGetSymbolAddress((void**)&srcH, g_srcH);
    cudaGetSymbolAddress((void**)&srcL, g_srcL);
    cudaGetSymbolAddress((void**)&wkvH, g_wkvH);
    cudaGetSymbolAddress((void**)&wkvL, g_wkvL);

    static bool attr_set = false;
    if (!attr_set) {
        cudaFuncSetAttribute(gemm_kv_bf16,
                             cudaFuncAttributeMaxDynamicSharedMemorySize, 81920);
        attr_set = true;
    }

    const dim3 blk(256);

    // pre-pass: bf16 hi/lo conversion of src and transposed Wk|Wv
    convert_src_kernel<<<(32768 * 1024 / 4 + 255) / 256, blk>>>(src, srcH, srcL, 32768 * 1024 / 4);
    conv_wkv_kernel<<<dim3(64, 32), dim3(32, 8)>>>(Wk, Wv, wkvH, wkvL);

    // fused K|V projection: [32768,1024] @ [1024,2048]
    gemm_kv_bf16<<<dim3(16, 256), blk, 81920>>>(srcH, srcL, wkvH, wkvL, bk, bv, KV);

    // Q projection: [1024,256] @ [256,1024]
    gemm_tc<false><<<dim3(8, 8), blk>>>(tgt, 256, Wq, 1024, bq, Qp, 1024, 256);

    // attention (split-T x2)
    attn_kernel<<<512, blk>>>(Qp, KV, Ap);

    // output projection + residual + LN1
    gemm_tc<false><<<dim3(2, 8), blk>>>(Ap, 1024, Wo, 256, bo, T1, 256, 1024);
    add_ln_kernel<<<1024, 256>>>(T1, tgt, ln1g, ln1b, X1);

    // FFN
    gemm_tc<true ><<<dim3(8, 8), blk>>>(X1, 256, W1, 1024, bf1, F1, 1024, 256);
    gemm_tc<false><<<dim3(2, 8), blk>>>(F1, 1024, W2, 256, bf2, T1, 256, 1024);

    // residual + LN3 -> output
    add_ln_kernel<<<1024, 256>>>(T1, X1, ln3g, ln3b, out);
}

// round 7
// speedup vs baseline: 1.1404x; 1.1404x over previous
#include <cuda_runtime.h>
#include <cuda_bf16.h>
#include <cuda_fp16.h>
#include <math.h>
#include <stdint.h>

typedef unsigned short ushort_t;

// ---------------------------------------------------------------------------
// Scratch (device globals; no runtime allocation allowed)
// ---------------------------------------------------------------------------
__device__ float    g_KV[(size_t)32768 * 2048];     // [B*S, 2048]: K | V (fp32)
__device__ ushort_t g_srcH[(size_t)32768 * 1024];   // src fp16 hi
__device__ ushort_t g_srcL[(size_t)32768 * 1024];   // src fp16 lo (residual)
__device__ ushort_t g_wkvH[(size_t)2048 * 1024];    // [Wk|Wv]^T fp16 hi : [n][k]
__device__ float    g_Q [(size_t)1024 * 1024];
__device__ float    g_A [(size_t)1024 * 1024];
__device__ float    g_F1[(size_t)1024 * 1024];
__device__ float    g_T1[(size_t)1024 * 256];
__device__ float    g_X1[(size_t)1024 * 256];

// ---------------------------------------------------------------------------
// helpers
// ---------------------------------------------------------------------------
// bf16 hi/lo split (for the small 3-term GEMMs)
__device__ __forceinline__ void split2(float x0, float x1, uint32_t& hi, uint32_t& lo) {
    __nv_bfloat16 h0 = __float2bfloat16(x0), h1 = __float2bfloat16(x1);
    float r0 = x0 - __bfloat162float(h0);
    float r1 = x1 - __bfloat162float(h1);
    __nv_bfloat16 l0 = __float2bfloat16(r0), l1 = __float2bfloat16(r1);
    hi = (uint32_t)__bfloat16_as_ushort(h0) | ((uint32_t)__bfloat16_as_ushort(h1) << 16);
    lo = (uint32_t)__bfloat16_as_ushort(l0) | ((uint32_t)__bfloat16_as_ushort(l1) << 16);
}

// fp16 hi/lo split (for the big 2-term KV GEMM)
__device__ __forceinline__ void split2h(float x0, float x1, uint32_t& hi, uint32_t& lo) {
    __half h0 = __float2half_rn(x0), h1 = __float2half_rn(x1);
    float r0 = x0 - __half2float(h0);
    float r1 = x1 - __half2float(h1);
    __half l0 = __float2half_rn(r0), l1 = __float2half_rn(r1);
    hi = (uint32_t)__half_as_ushort(h0) | ((uint32_t)__half_as_ushort(h1) << 16);
    lo = (uint32_t)__half_as_ushort(l0) | ((uint32_t)__half_as_ushort(l1) << 16);
}

__device__ __forceinline__ void mma16816bf(float* c, const uint32_t* a, uint32_t b0, uint32_t b1) {
    asm volatile(
        "mma.sync.aligned.m16n8k16.row.col.f32.bf16.bf16.f32 "
        "{%0,%1,%2,%3}, {%4,%5,%6,%7}, {%8,%9}, {%0,%1,%2,%3};"
        : "+f"(c[0]), "+f"(c[1]), "+f"(c[2]), "+f"(c[3])
        : "r"(a[0]), "r"(a[1]), "r"(a[2]), "r"(a[3]), "r"(b0), "r"(b1));
}

__device__ __forceinline__ void mma16816h(float* c, const uint32_t* a, uint32_t b0, uint32_t b1) {
    asm volatile(
        "mma.sync.aligned.m16n8k16.row.col.f32.f16.f16.f32 "
        "{%0,%1,%2,%3}, {%4,%5,%6,%7}, {%8,%9}, {%0,%1,%2,%3};"
        : "+f"(c[0]), "+f"(c[1]), "+f"(c[2]), "+f"(c[3])
        : "r"(a[0]), "r"(a[1]), "r"(a[2]), "r"(a[3]), "r"(b0), "r"(b1));
}

__device__ __forceinline__ void cp16(void* sdst, const void* gsrc) {
    uint32_t s = (uint32_t)__cvta_generic_to_shared(sdst);
    asm volatile("cp.async.cg.shared.global [%0], [%1], 16;" :: "r"(s), "l"(gsrc));
}

// ---------------------------------------------------------------------------
// pre-pass: fp32 -> fp16 hi/lo (flat, float4 granularity)
// ---------------------------------------------------------------------------
__global__ __launch_bounds__(256) void convert_src_kernel(
    const float* __restrict__ x, ushort_t* __restrict__ H, ushort_t* __restrict__ L, int n4)
{
    int i = blockIdx.x * blockDim.x + threadIdx.x;
    if (i >= n4) return;
    float4 v = ((const float4*)x)[i];
    uint32_t h0, l0, h1, l1;
    split2h(v.x, v.y, h0, l0);
    split2h(v.z, v.w, h1, l1);
    ((uint2*)H)[i] = make_uint2(h0, h1);
    ((uint2*)L)[i] = make_uint2(l0, l1);
}

// ---------------------------------------------------------------------------
// pre-pass: WT[n][k] = (n<1024 ? Wk[k][n] : Wv[k][n-1024]) -> fp16 hi only
// grid (2048/32, 1024/32), block (32,8)
// ---------------------------------------------------------------------------
__global__ __launch_bounds__(256) void conv_wkv_kernel(
    const float* __restrict__ Wk, const float* __restrict__ Wv,
    ushort_t* __restrict__ H)
{
    __shared__ float tile[32][33];
    const int n0 = blockIdx.x * 32, k0 = blockIdx.y * 32;
    const float* W = (n0 < 1024) ? Wk : Wv;
    const int nofs = (n0 < 1024) ? n0 : n0 - 1024;
    for (int r = threadIdx.y; r < 32; r += 8)
        tile[r][threadIdx.x] = W[(size_t)(k0 + r) * 1024 + nofs + threadIdx.x];
    __syncthreads();
    for (int r = threadIdx.y; r < 32; r += 8) {
        float v = tile[threadIdx.x][r];
        size_t o = (size_t)(n0 + r) * 1024 + k0 + threadIdx.x;
        H[o] = __half_as_ushort(__float2half_rn(v));
    }
}

// ---------------------------------------------------------------------------
// Fused KV GEMM (fp16 2-term): C[32768,2048] = src @ WkvT^T + bias(bk|bv)
// A exact (hi+lo fp16), B fp16 hi only. 2 MMAs per K16 step per tile.
// Block tile 128x128, BK=32, cp.async double-buffered, 256 threads.
// Stage layout: AsH | AsL | BsH, each 128*40 halves (10240 B) -> 30720 B/stage.
// ---------------------------------------------------------------------------
#define TP 40              // smem pitch in halves (32 + 8 pad)
#define TILE_H (128 * TP)  // halves per component buffer
#define KV_STAGE_H (3 * TILE_H)
#define KV_SMEM_BYTES (2 * KV_STAGE_H * 2)

__device__ __forceinline__ void kv_load_tiles(
    ushort_t* stage,
    const ushort_t* __restrict__ srcH, const ushort_t* __restrict__ srcL,
    const ushort_t* __restrict__ wtH,
    int r0, int c0, int kb, int tid)
{
    ushort_t* AsH = stage;
    ushort_t* AsL = stage + TILE_H;
    ushort_t* BsH = stage + 2 * TILE_H;
#pragma unroll
    for (int j = 0; j < 2; j++) {
        int cc  = tid + 256 * j;         // 0..511
        int row = cc >> 2;
        int c16 = (cc & 3) * 8;          // halves
        size_t ga = (size_t)(r0 + row) * 1024 + kb + c16;
        cp16(&AsH[row * TP + c16], srcH + ga);
        cp16(&AsL[row * TP + c16], srcL + ga);
        size_t gb = (size_t)(c0 + row) * 1024 + kb + c16;
        cp16(&BsH[row * TP + c16], wtH + gb);
    }
}

__global__ __launch_bounds__(256) void gemm_kv_f16(
    const ushort_t* __restrict__ srcH, const ushort_t* __restrict__ srcL,
    const ushort_t* __restrict__ wtH,
    const float* __restrict__ bk, const float* __restrict__ bv,
    float* __restrict__ C)
{
    extern __shared__ ushort_t smem[];

    const int tid  = threadIdx.x;
    const int lane = tid & 31;
    const int wid  = tid >> 5;
    const int wm   = wid & 3;
    const int wn   = wid >> 2;
    const int g    = lane >> 2;
    const int tig  = lane & 3;

    const int r0 = blockIdx.y * 128;
    const int c0 = blockIdx.x * 128;

    float acc[2][8][4];
#pragma unroll
    for (int mt = 0; mt < 2; mt++)
#pragma unroll
        for (int nt = 0; nt < 8; nt++)
#pragma unroll
            for (int j = 0; j < 4; j++) acc[mt][nt][j] = 0.f;

    kv_load_tiles(smem, srcH, srcL, wtH, r0, c0, 0, tid);
    asm volatile("cp.async.commit_group;" ::: "memory");

    int buf = 0;
    for (int it = 0; it < 32; it++) {
        if (it < 31) {
            kv_load_tiles(smem + (buf ^ 1) * KV_STAGE_H,
                          srcH, srcL, wtH, r0, c0, (it + 1) * 32, tid);
            asm volatile("cp.async.commit_group;" ::: "memory");
            asm volatile("cp.async.wait_group 1;" ::: "memory");
        } else {
            asm volatile("cp.async.wait_group 0;" ::: "memory");
        }
        __syncthreads();

        const ushort_t* aH = smem + buf * KV_STAGE_H;
        const ushort_t* aL = aH + TILE_H;
        const ushort_t* bH = aH + 2 * TILE_H;

#pragma unroll
        for (int ks = 0; ks < 32; ks += 16) {
            uint32_t AHf[2][4], ALf[2][4];
#pragma unroll
            for (int mt = 0; mt < 2; mt++) {
                int rA = wm * 32 + mt * 16 + g;
                int cA = ks + tig * 2;
                AHf[mt][0] = *(const uint32_t*)&aH[rA * TP + cA];
                AHf[mt][1] = *(const uint32_t*)&aH[(rA + 8) * TP + cA];
                AHf[mt][2] = *(const uint32_t*)&aH[rA * TP + cA + 8];
                AHf[mt][3] = *(const uint32_t*)&aH[(rA + 8) * TP + cA + 8];
                ALf[mt][0] = *(const uint32_t*)&aL[rA * TP + cA];
                ALf[mt][1] = *(const uint32_t*)&aL[(rA + 8) * TP + cA];
                ALf[mt][2] = *(const uint32_t*)&aL[rA * TP + cA + 8];
                ALf[mt][3] = *(const uint32_t*)&aL[(rA + 8) * TP + cA + 8];
            }
#pragma unroll
            for (int nt = 0; nt < 8; nt++) {
                int n  = wn * 64 + nt * 8 + g;
                int kk = ks + tig * 2;
                uint32_t bH0 = *(const uint32_t*)&bH[n * TP + kk];
                uint32_t bH1 = *(const uint32_t*)&bH[n * TP + kk + 8];
#pragma unroll
                for (int mt = 0; mt < 2; mt++) {
                    mma16816h(acc[mt][nt], AHf[mt], bH0, bH1);
                    mma16816h(acc[mt][nt], ALf[mt], bH0, bH1);
                }
            }
        }
        __syncthreads();
        buf ^= 1;
    }

    // epilogue
#pragma unroll
    for (int mt = 0; mt < 2; mt++) {
        int r = r0 + wm * 32 + mt * 16 + g;
#pragma unroll
        for (int nt = 0; nt < 8; nt++) {
            int col = c0 + wn * 64 + nt * 8 + tig * 2;
            float b0 = (col < 1024) ? bk[col] : bv[col - 1024];
            float b1 = (col + 1 < 1024) ? bk[col + 1] : bv[col + 1 - 1024];
            *(float2*)(C + (size_t)r * 2048 + col) =
                make_float2(acc[mt][nt][0] + b0, acc[mt][nt][1] + b1);
            *(float2*)(C + (size_t)(r + 8) * 2048 + col) =
                make_float2(acc[mt][nt][2] + b0, acc[mt][nt][3] + b1);
        }
    }
}

// ---------------------------------------------------------------------------
// Small GEMM (fp32 in, in-loop bf16 hi/lo split x3, mma.sync) — proven path.
// ---------------------------------------------------------------------------
#define A_PITCH 40
#define B_PITCH 136

template<bool RELU>
__global__ __launch_bounds__(256) void gemm_tc(
    const float* __restrict__ A, int lda,
    const float* __restrict__ W, int ldb,
    const float* __restrict__ bias,
    float* __restrict__ C, int ldc, int K)
{
    __shared__ unsigned short AsH[128 * A_PITCH];
    __shared__ unsigned short AsL[128 * A_PITCH];
    __shared__ unsigned short BsH[32 * B_PITCH];
    __shared__ unsigned short BsL[32 * B_PITCH];

    const int tid  = threadIdx.x;
    const int lane = tid & 31;
    const int wid  = tid >> 5;
    const int wm   = wid & 3;
    const int wn   = wid >> 2;
    const int g    = lane >> 2;
    const int tig  = lane & 3;

    const int r0 = blockIdx.y * 128;
    const int c0 = blockIdx.x * 128;

    float acc[2][8][4];
#pragma unroll
    for (int mt = 0; mt < 2; mt++)
#pragma unroll
        for (int nt = 0; nt < 8; nt++)
#pragma unroll
            for (int j = 0; j < 4; j++) acc[mt][nt][j] = 0.f;

    for (int kb = 0; kb < K; kb += 32) {
#pragma unroll
        for (int i = 0; i < 4; i++) {
            int flat = tid + 256 * i;
            int row = flat >> 3;
            int kc  = (flat & 7) * 4;
            float4 a4 = *(const float4*)(A + (size_t)(r0 + row) * lda + kb + kc);
            uint32_t hi, lo;
            split2(a4.x, a4.y, hi, lo);
            *(uint32_t*)&AsH[row * A_PITCH + kc] = hi;
            *(uint32_t*)&AsL[row * A_PITCH + kc] = lo;
            split2(a4.z, a4.w, hi, lo);
            *(uint32_t*)&AsH[row * A_PITCH + kc + 2] = hi;
            *(uint32_t*)&AsL[row * A_PITCH + kc + 2] = lo;
        }
#pragma unroll
        for (int i = 0; i < 4; i++) {
            int flat = tid + 256 * i;
            int kr = flat >> 5;
            int nc = (flat & 31) * 4;
            float4 b4 = *(const float4*)(W + (size_t)(kb + kr) * ldb + c0 + nc);
            uint32_t hi, lo;
            split2(b4.x, b4.y, hi, lo);
            *(uint32_t*)&BsH[kr * B_PITCH + nc] = hi;
            *(uint32_t*)&BsL[kr * B_PITCH + nc] = lo;
            split2(b4.z, b4.w, hi, lo);
            *(uint32_t*)&BsH[kr * B_PITCH + nc + 2] = hi;
            *(uint32_t*)&BsL[kr * B_PITCH + nc + 2] = lo;
        }
        __syncthreads();

#pragma unroll
        for (int ks = 0; ks < 32; ks += 16) {
            uint32_t aH[2][4], aL[2][4];
#pragma unroll
            for (int mt = 0; mt < 2; mt++) {
                int rA = wm * 32 + mt * 16 + g;
                int cA = ks + tig * 2;
                aH[mt][0] = *(const uint32_t*)&AsH[rA * A_PITCH + cA];
                aH[mt][1] = *(const uint32_t*)&AsH[(rA + 8) * A_PITCH + cA];
                aH[mt][2] = *(const uint32_t*)&AsH[rA * A_PITCH + cA + 8];
                aH[mt][3] = *(const uint32_t*)&AsH[(rA + 8) * A_PITCH + cA + 8];
                aL[mt][0] = *(const uint32_t*)&AsL[rA * A_PITCH + cA];
                aL[mt][1] = *(const uint32_t*)&AsL[(rA + 8) * A_PITCH + cA];
                aL[mt][2] = *(const uint32_t*)&AsL[rA * A_PITCH + cA + 8];
                aL[mt][3] = *(const uint32_t*)&AsL[(rA + 8) * A_PITCH + cA + 8];
            }
#pragma unroll
            for (int nt = 0; nt < 8; nt++) {
                int col = wn * 64 + nt * 8 + g;
                int rb  = (ks + tig * 2) * B_PITCH + col;
                uint32_t bH0 = (uint32_t)BsH[rb] | ((uint32_t)BsH[rb + B_PITCH] << 16);
                uint32_t bL0 = (uint32_t)BsL[rb] | ((uint32_t)BsL[rb + B_PITCH] << 16);
                int rb8 = rb + 8 * B_PITCH;
                uint32_t bH1 = (uint32_t)BsH[rb8] | ((uint32_t)BsH[rb8 + B_PITCH] << 16);
                uint32_t bL1 = (uint32_t)BsL[rb8] | ((uint32_t)BsL[rb8 + B_PITCH] << 16);
#pragma unroll
                for (int mt = 0; mt < 2; mt++) {
                    mma16816bf(acc[mt][nt], aH[mt], bH0, bH1);
                    mma16816bf(acc[mt][nt], aH[mt], bL0, bL1);
                    mma16816bf(acc[mt][nt], aL[mt], bH0, bH1);
                }
            }
        }
        __syncthreads();
    }

#pragma unroll
    for (int mt = 0; mt < 2; mt++) {
        int r = r0 + wm * 32 + mt * 16 + g;
#pragma unroll
        for (int nt = 0; nt < 8; nt++) {
            int col = c0 + wn * 64 + nt * 8 + tig * 2;
            float b0 = bias[col], b1 = bias[col + 1];
            float v0 = acc[mt][nt][0] + b0;
            float v1 = acc[mt][nt][1] + b1;
            float v2 = acc[mt][nt][2] + b0;
            float v3 = acc[mt][nt][3] + b1;
            if (RELU) {
                v0 = fmaxf(v0, 0.f); v1 = fmaxf(v1, 0.f);
                v2 = fmaxf(v2, 0.f); v3 = fmaxf(v3, 0.f);
            }
            *(float2*)(C + (size_t)r * ldc + col)       = make_float2(v0, v1);
            *(float2*)(C + (size_t)(r + 8) * ldc + col) = make_float2(v2, v3);
        }
    }
}

// ---------------------------------------------------------------------------
// Flash attention, split-T, cp.async double-buffered K/V.
// One block per (b,h,half): 32 queries, 256 threads, 64 chunks of 32 keys.
// ---------------------------------------------------------------------------
#define KV_PITCH 68   // floats: 64 + 4 pad; keeps 16B alignment for cp.async

__global__ __launch_bounds__(256) void attn_kernel(
    const float* __restrict__ Q,
    const float* __restrict__ KV,
    float* __restrict__ Aout)
{
    __shared__ float Qs[32][64];
    __shared__ float Ks[2][32][KV_PITCH];
    __shared__ float Vs[2][32][KV_PITCH];
    __shared__ float Ss[32][33];

    const int bh = blockIdx.x >> 1;
    const int half = blockIdx.x & 1;
    const int b = bh >> 4, h = bh & 15;
    const float* Qb = Q  + (size_t)(b * 64 + half * 32) * 1024 + h * 64;
    const float* Kb = KV + (size_t)b * 2048 * 2048 + h * 64;
    const float* Vb = Kb + 1024;

    const int tid = threadIdx.x;
    const int tx = tid & 15, ty = tid >> 4;

    // async loader for one 32-key chunk: 1024 x 16B (K:512, V:512) / 256 thr
    auto load_kv = [&](int st, int s0) {
#pragma unroll
        for (int j = 0; j < 4; j++) {
            int c    = tid + 256 * j;          // 0..1023
            int isV  = c >> 9;                 // 0:K 1:V
            int cc   = c & 511;
            int row  = cc >> 4;                // 0..31
            int q4   = (cc & 15) * 4;          // float offset
            const float* gsrc = (isV ? Vb : Kb) + (size_t)(s0 + row) * 2048 + q4;
            float* sdst = isV ? &Vs[st][row][q4] : &Ks[st][row][q4];
            cp16(sdst, gsrc);
        }
    };

    for (int f = tid; f < 2048; f += 256) {
        int t = f >> 6, d = f & 63;
        Qs[t][d] = Qb[(size_t)t * 1024 + d] * 0.125f;
    }

    float out[2][4];
    float m[2], l[2];
#pragma unroll
    for (int i = 0; i < 2; i++) {
        m[i] = -1e30f; l[i] = 0.f;
#pragma unroll
        for (int j = 0; j < 4; j++) out[i][j] = 0.f;
    }

    load_kv(0, 0);
    asm volatile("cp.async.commit_group;" ::: "memory");

    int buf = 0;
    for (int it = 0; it < 64; it++) {
        if (it < 63) {
            load_kv(buf ^ 1, (it + 1) * 32);
            asm volatile("cp.async.commit_group;" ::: "memory");
            asm volatile("cp.async.wait_group 1;" ::: "memory");
        } else {
            asm volatile("cp.async.wait_group 0;" ::: "memory");
        }
        __syncthreads();

        float r[2][2];
#pragma unroll
        for (int i = 0; i < 2; i++) { r[i][0] = 0.f; r[i][1] = 0.f; }
#pragma unroll 8
        for (int d = 0; d < 64; d++) {
            float k0 = Ks[buf][tx][d];
            float k1 = Ks[buf][tx + 16][d];
#pragma unroll
            for (int i = 0; i < 2; i++) {
                float q = Qs[ty + 16 * i][d];
                r[i][0] = fmaf(q, k0, r[i][0]);
                r[i][1] = fmaf(q, k1, r[i][1]);
            }
        }

#pragma unroll
        for (int i = 0; i < 2; i++) {
            int t = ty + 16 * i;
            float cm = fmaxf(r[i][0], r[i][1]);
#pragma unroll
            for (int off = 8; off > 0; off >>= 1)
                cm = fmaxf(cm, __shfl_xor_sync(0xffffffffu, cm, off, 16));
            float mn = fmaxf(m[i], cm);
            float f_old = __expf(m[i] - mn);
            float p0 = __expf(r[i][0] - mn);
            float p1 = __expf(r[i][1] - mn);
            Ss[t][tx]      = p0;
            Ss[t][tx + 16] = p1;
            float cs = p0 + p1;
#pragma unroll
            for (int off = 8; off > 0; off >>= 1)
                cs += __shfl_xor_sync(0xffffffffu, cs, off, 16);
            l[i] = l[i] * f_old + cs;
            m[i] = mn;
#pragma unroll
            for (int j = 0; j < 4; j++) out[i][j] *= f_old;
        }
        __syncwarp();   // Ss row written by this warp's 16-groups, read below

#pragma unroll 4
        for (int s = 0; s < 32; s++) {
            float4 v = *(const float4*)&Vs[buf][s][tx * 4];
#pragma unroll
            for (int i = 0; i < 2; i++) {
                float p = Ss[ty + 16 * i][s];
                out[i][0] = fmaf(p, v.x, out[i][0]);
                out[i][1] = fmaf(p, v.y, out[i][1]);
                out[i][2] = fmaf(p, v.z, out[i][2]);
                out[i][3] = fmaf(p, v.w, out[i][3]);
            }
        }
        __syncthreads();
        buf ^= 1;
    }

#pragma unroll
    for (int i = 0; i < 2; i++) {
        int t = ty + 16 * i;
        float inv = 1.f / l[i];
        float* Ap = Aout + (size_t)(b * 64 + half * 32 + t) * 1024 + h * 64 + tx * 4;
#pragma unroll
        for (int j = 0; j < 4; j++) Ap[j] = out[i][j] * inv;
    }
}

// ---------------------------------------------------------------------------
// out[row] = LayerNorm(pre[row] + res[row]) * g + b   (row length 256)
// ---------------------------------------------------------------------------
__global__ __launch_bounds__(256) void add_ln_kernel(
    const float* __restrict__ pre,
    const float* __restrict__ res,
    const float* __restrict__ g,
    const float* __restrict__ bta,
    float* __restrict__ out)
{
    const int row = blockIdx.x;
    const int t = threadIdx.x;
    const size_t idx = (size_t)row * 256 + t;

    float v = pre[idx] + res[idx];
    float s = v, s2 = v * v;
#pragma unroll
    for (int off = 16; off > 0; off >>= 1) {
        s  += __shfl_xor_sync(0xffffffffu, s,  off);
        s2 += __shfl_xor_sync(0xffffffffu, s2, off);
    }
    __shared__ float rs[8], rs2[8];
    const int w = t >> 5, lane = t & 31;
    if (lane == 0) { rs[w] = s; rs2[w] = s2; }
    __syncthreads();
    if (t < 32) {
        s  = (t < 8) ? rs[t]  : 0.f;
        s2 = (t < 8) ? rs2[t] : 0.f;
#pragma unroll
        for (int off = 4; off > 0; off >>= 1) {
            s  += __shfl_xor_sync(0xffffffffu, s,  off);
            s2 += __shfl_xor_sync(0xffffffffu, s2, off);
        }
        if (t == 0) { rs[0] = s; rs2[0] = s2; }
    }
    __syncthreads();
    float mean = rs[0] * (1.f / 256.f);
    float var  = rs2[0] * (1.f / 256.f) - mean * mean;
    out[idx] = (v - mean) * rsqrtf(var + 1e-5f) * g[t] + bta[t];
}

// ---------------------------------------------------------------------------
extern "C" void kernel_launch(void* const* d_in, const int* in_sizes, int n_in,
                              void* d_out, int out_size)
{
    const float* src  = (const float*)d_in[0];
    const float* tgt  = (const float*)d_in[1];
    const float* Wq   = (const float*)d_in[2];
    const float* bq   = (const float*)d_in[3];
    const float* Wk   = (const float*)d_in[4];
    const float* bk   = (const float*)d_in[5];
    const float* Wv   = (const float*)d_in[6];
    const float* bv   = (const float*)d_in[7];
    const float* Wo   = (const float*)d_in[8];
    const float* bo   = (const float*)d_in[9];
    const float* ln1g = (const float*)d_in[10];
    const float* ln1b = (const float*)d_in[11];
    const float* W1   = (const float*)d_in[12];
    const float* bf1  = (const float*)d_in[13];
    const float* W2   = (const float*)d_in[14];
    const float* bf2  = (const float*)d_in[15];
    const float* ln3g = (const float*)d_in[16];
    const float* ln3b = (const float*)d_in[17];
    float* out = (float*)d_out;

    float *KV, *Qp, *Ap, *F1, *T1, *X1;
    ushort_t *srcH, *srcL, *wkvH;
    cudaGetSymbolAddress((void**)&KV, g_KV);
    cudaGetSymbolAddress((void**)&Qp, g_Q);
    cudaGetSymbolAddress((void**)&Ap, g_A);
    cudaGetSymbolAddress((void**)&F1, g_F1);
    cudaGetSymbolAddress((void**)&T1, g_T1);
    cudaGetSymbolAddress((void**)&X1, g_X1);
    cudaGetSymbolAddress((void**)&srcH, g_srcH);
    cudaGetSymbolAddress((void**)&srcL, g_srcL);
    cudaGetSymbolAddress((void**)&wkvH, g_wkvH);

    static bool attr_set = false;
    if (!attr_set) {
        cudaFuncSetAttribute(gemm_kv_f16,
                             cudaFuncAttributeMaxDynamicSharedMemorySize, KV_SMEM_BYTES);
        attr_set = true;
    }

    const dim3 blk(256);

    // pre-pass: fp16 hi/lo conversion of src; fp16 hi of transposed Wk|Wv
    convert_src_kernel<<<(32768 * 1024 / 4 + 255) / 256, blk>>>(src, srcH, srcL, 32768 * 1024 / 4);
    conv_wkv_kernel<<<dim3(64, 32), dim3(32, 8)>>>(Wk, Wv, wkvH);

    // fused K|V projection (fp16 2-term): [32768,1024] @ [1024,2048]
    gemm_kv_f16<<<dim3(16, 256), blk, KV_SMEM_BYTES>>>(srcH, srcL, wkvH, bk, bv, KV);

    // Q projection: [1024,256] @ [256,1024]
    gemm_tc<false><<<dim3(8, 8), blk>>>(tgt, 256, Wq, 1024, bq, Qp, 1024, 256);

    // attention (split-T x2, cp.async pipelined)
    attn_kernel<<<512, blk>>>(Qp, KV, Ap);

    // output projection + residual + LN1
    gemm_tc<false><<<dim3(2, 8), blk>>>(Ap, 1024, Wo, 256, bo, T1, 256, 1024);
    add_ln_kernel<<<1024, 256>>>(T1, tgt, ln1g, ln1b, X1);

    // FFN
    gemm_tc<true ><<<dim3(8, 8), blk>>>(X1, 256, W1, 1024, bf1, F1, 1024, 256);
    gemm_tc<false><<<dim3(2, 8), blk>>>(F1, 1024, W2, 256, bf2, T1, 256, 1024);

    // residual + LN3 -> output
    add_ln_kernel<<<1024, 256>>>(T1, X1, ln3g, ln3b, out);
}